// round 16
// baseline (speedup 1.0000x reference)
#include <cuda_runtime.h>
#include <math.h>

#define B_  4096
#define H_  200
#define EMB_ 128
#define HID_ 64
#define HID2_ 32
#define NTHREADS 256
#define HSTRIDE 132     // hist row stride in floats (padded, 16B aligned)
#define H1STRIDE 68     // layer1 output row stride (padded, 16B aligned)

// ---- shared memory layout (offsets in floats, all float4-aligned) ----
#define OFF_HIST   0                       // 200*132 = 26400
#define OFF_W1     26400                   // 128*64  = 8192
#define OFF_W2     34592                   // 64*32   = 2048
#define OFF_H1     36640                   // 64*68   = 4352
#define OFF_CAND   40992                   // 128
#define OFF_WFULL  41120                   // 200
#define OFF_SCORES 41320                   // 200
#define OFF_CPART  41520                   // 64
#define OFF_W3     41584                   // 32
#define OFF_B2     41616                   // 32
#define OFF_RED    41648                   // 32
#define OFF_MISC   41680                   // 4: [0]=count(int) [1]=bmax [2]=bsum [3]=b3
#define OFF_IDX    41684                   // 200 ints
#define SMEM_FLOATS 41884
#define SMEM_BYTES (SMEM_FLOATS * 4)

#define FMA4(ACCROW, AV, W)                      \
    ACCROW[0] = fmaf((AV), (W).x, ACCROW[0]);    \
    ACCROW[1] = fmaf((AV), (W).y, ACCROW[1]);    \
    ACCROW[2] = fmaf((AV), (W).z, ACCROW[2]);    \
    ACCROW[3] = fmaf((AV), (W).w, ACCROW[3]);

__global__ __launch_bounds__(NTHREADS, 1)
void attn_agg_kernel(const float* __restrict__ hist,
                     const float* __restrict__ cand,
                     const float* __restrict__ W1g,
                     const float* __restrict__ b1g,
                     const float* __restrict__ W2g,
                     const float* __restrict__ b2g,
                     const float* __restrict__ W3g,
                     const float* __restrict__ b3g,
                     const int*   __restrict__ maskg,
                     float*       __restrict__ out)
{
    extern __shared__ float sm[];
    float* sh_hist   = sm + OFF_HIST;
    float* sh_W1     = sm + OFF_W1;
    float* sh_W2     = sm + OFF_W2;
    float* sh_H1     = sm + OFF_H1;
    float* sh_cand   = sm + OFF_CAND;
    float* sh_wfull  = sm + OFF_WFULL;
    float* sh_scores = sm + OFF_SCORES;
    float* sh_cpart  = sm + OFF_CPART;
    float* sh_W3     = sm + OFF_W3;
    float* sh_b2     = sm + OFF_B2;
    float* sh_red    = sm + OFF_RED;
    float* sh_misc   = sm + OFF_MISC;
    int*   sh_count  = (int*)(sm + OFF_MISC);
    int*   sh_idx    = (int*)(sm + OFF_IDX);

    const int tid  = threadIdx.x;
    const int b    = blockIdx.x;
    const int lane = tid & 31;
    const int wrp  = tid >> 5;

    // ---- Phase A: compaction (warp 0) + cooperative weight loads (all) ----
    if (wrp == 0) {
        int total = 0;
        const int* mrow = maskg + (size_t)b * H_;
        for (int base = 0; base < H_; base += 32) {
            int h = base + lane;
            int m = (h < H_) ? mrow[h] : 0;
            unsigned bal = __ballot_sync(0xffffffffu, m != 0);
            int rank = __popc(bal & ((1u << lane) - 1u));
            if (m) sh_idx[total + rank] = h;
            total += __popc(bal);
        }
        if (lane == 0) *sh_count = total;
    }
    {
        const float4* W14 = (const float4*)W1g;
        for (int t = tid; t < (EMB_ * HID_) / 4; t += NTHREADS)
            ((float4*)sh_W1)[t] = W14[t];
        const float4* W24 = (const float4*)W2g;
        for (int t = tid; t < (HID_ * HID2_) / 4; t += NTHREADS)
            ((float4*)sh_W2)[t] = W24[t];
        if (tid < 32) { sh_W3[tid] = W3g[tid]; sh_b2[tid] = b2g[tid]; }
        if (tid >= 32 && tid < 64)
            ((float4*)sh_cand)[tid - 32] = ((const float4*)(cand + (size_t)b * EMB_))[tid - 32];
        if (tid == 64) sh_misc[3] = b3g[0];
    }
    __syncthreads();

    int U = *sh_count;
    if (U == 0) {  // all masked: softmax reduces to softmax of raw scores over all h
        for (int h = tid; h < H_; h += NTHREADS) sh_idx[h] = h;
        U = H_;
        __syncthreads();
    }

    // ---- Phase B: candidate part of layer1 (per-b, tiny) ----
    if (tid < HID_) {
        float s = b1g[tid];
        const float* Wb = W1g + (size_t)EMB_ * HID_ + tid;
        #pragma unroll 4
        for (int k = 0; k < EMB_; k++)
            s = fmaf(sh_cand[k], Wb[(size_t)k * HID_], s);
        sh_cpart[tid] = s;
    }

    // ---- Phase C: load ONLY unmasked hist rows (compacted) into SMEM ----
    {
        const float4* hist4 = (const float4*)(hist + (size_t)b * (H_ * EMB_));
        int n = U * 32;
        for (int t = tid; t < n; t += NTHREADS) {
            int u = t >> 5, c = t & 31;
            float4 v = hist4[(size_t)sh_idx[u] * 32 + c];
            *(float4*)&sh_hist[u * HSTRIDE + 4 * c] = v;
        }
    }
    for (int t = tid; t < H_; t += NTHREADS) sh_wfull[t] = 0.f;
    __syncthreads();

    const float b3v = sh_misc[3];

    // ---- Phase D: MLP over compacted rows, 64-row chunks ----
    for (int cb = 0; cb < U; cb += 64) {
        // layer1: [64,128] @ [128,64], 4x4 register tiles, 256 threads
        {
            const int ty = tid >> 4, tx = tid & 15;
            const float* hrow[4];
            #pragma unroll
            for (int i = 0; i < 4; i++) {
                int r = cb + 4 * ty + i;
                if (r > U - 1) r = U - 1;       // clamp (garbage rows discarded later)
                hrow[i] = sh_hist + r * HSTRIDE;
            }
            float acc[4][4];
            #pragma unroll
            for (int i = 0; i < 4; i++)
                #pragma unroll
                for (int j = 0; j < 4; j++) acc[i][j] = 0.f;

            const float* wp = sh_W1 + 4 * tx;
            #pragma unroll 4
            for (int k = 0; k < EMB_; k += 4) {
                float4 a0 = *(const float4*)(hrow[0] + k);
                float4 a1 = *(const float4*)(hrow[1] + k);
                float4 a2 = *(const float4*)(hrow[2] + k);
                float4 a3 = *(const float4*)(hrow[3] + k);
                float4 w0 = *(const float4*)(wp + (k + 0) * HID_);
                float4 w1 = *(const float4*)(wp + (k + 1) * HID_);
                float4 w2 = *(const float4*)(wp + (k + 2) * HID_);
                float4 w3 = *(const float4*)(wp + (k + 3) * HID_);
                FMA4(acc[0], a0.x, w0) FMA4(acc[1], a1.x, w0) FMA4(acc[2], a2.x, w0) FMA4(acc[3], a3.x, w0)
                FMA4(acc[0], a0.y, w1) FMA4(acc[1], a1.y, w1) FMA4(acc[2], a2.y, w1) FMA4(acc[3], a3.y, w1)
                FMA4(acc[0], a0.z, w2) FMA4(acc[1], a1.z, w2) FMA4(acc[2], a2.z, w2) FMA4(acc[3], a3.z, w2)
                FMA4(acc[0], a0.w, w3) FMA4(acc[1], a1.w, w3) FMA4(acc[2], a2.w, w3) FMA4(acc[3], a3.w, w3)
            }
            float4 cp = *(const float4*)(sh_cpart + 4 * tx);
            #pragma unroll
            for (int i = 0; i < 4; i++) {
                float4 v;
                v.x = fmaxf(acc[i][0] + cp.x, 0.f);
                v.y = fmaxf(acc[i][1] + cp.y, 0.f);
                v.z = fmaxf(acc[i][2] + cp.z, 0.f);
                v.w = fmaxf(acc[i][3] + cp.w, 0.f);
                *(float4*)&sh_H1[(4 * ty + i) * H1STRIDE + 4 * tx] = v;
            }
        }
        __syncthreads();

        // layer2+3: [64,64]@[64,32] then dot with W3, 128 threads, 4x4 tiles
        if (tid < 128) {
            const int ty2 = tid >> 3, tx2 = tid & 7;
            const float* h1p = sh_H1 + (4 * ty2) * H1STRIDE;
            float acc2[4][4];
            #pragma unroll
            for (int i = 0; i < 4; i++)
                #pragma unroll
                for (int j = 0; j < 4; j++) acc2[i][j] = 0.f;

            const float* wp2 = sh_W2 + 4 * tx2;
            #pragma unroll 4
            for (int k = 0; k < HID_; k += 4) {
                float4 a0 = *(const float4*)(h1p + 0 * H1STRIDE + k);
                float4 a1 = *(const float4*)(h1p + 1 * H1STRIDE + k);
                float4 a2 = *(const float4*)(h1p + 2 * H1STRIDE + k);
                float4 a3 = *(const float4*)(h1p + 3 * H1STRIDE + k);
                float4 w0 = *(const float4*)(wp2 + (k + 0) * HID2_);
                float4 w1 = *(const float4*)(wp2 + (k + 1) * HID2_);
                float4 w2 = *(const float4*)(wp2 + (k + 2) * HID2_);
                float4 w3 = *(const float4*)(wp2 + (k + 3) * HID2_);
                FMA4(acc2[0], a0.x, w0) FMA4(acc2[1], a1.x, w0) FMA4(acc2[2], a2.x, w0) FMA4(acc2[3], a3.x, w0)
                FMA4(acc2[0], a0.y, w1) FMA4(acc2[1], a1.y, w1) FMA4(acc2[2], a2.y, w1) FMA4(acc2[3], a3.y, w1)
                FMA4(acc2[0], a0.z, w2) FMA4(acc2[1], a1.z, w2) FMA4(acc2[2], a2.z, w2) FMA4(acc2[3], a3.z, w2)
                FMA4(acc2[0], a0.w, w3) FMA4(acc2[1], a1.w, w3) FMA4(acc2[2], a2.w, w3) FMA4(acc2[3], a3.w, w3)
            }
            float4 bb  = *(const float4*)(sh_b2 + 4 * tx2);
            float4 w3c = *(const float4*)(sh_W3 + 4 * tx2);
            #pragma unroll
            for (int i = 0; i < 4; i++) {
                float v0 = fmaxf(acc2[i][0] + bb.x, 0.f);
                float v1 = fmaxf(acc2[i][1] + bb.y, 0.f);
                float v2 = fmaxf(acc2[i][2] + bb.z, 0.f);
                float v3 = fmaxf(acc2[i][3] + bb.w, 0.f);
                float p = v0 * w3c.x + v1 * w3c.y + v2 * w3c.z + v3 * w3c.w;
                p += __shfl_down_sync(0xffffffffu, p, 4, 8);
                p += __shfl_down_sync(0xffffffffu, p, 2, 8);
                p += __shfl_down_sync(0xffffffffu, p, 1, 8);
                if (tx2 == 0) {
                    int g = cb + 4 * ty2 + i;
                    if (g < U) sh_scores[g] = p + b3v;
                }
            }
        }
        __syncthreads();
    }

    // ---- Phase E: softmax over compacted scores ----
    float lmax = -3.0e38f;
    for (int u = tid; u < U; u += NTHREADS) lmax = fmaxf(lmax, sh_scores[u]);
    #pragma unroll
    for (int off = 16; off; off >>= 1)
        lmax = fmaxf(lmax, __shfl_xor_sync(0xffffffffu, lmax, off));
    if (lane == 0) sh_red[wrp] = lmax;
    __syncthreads();
    if (tid == 0) {
        float m = sh_red[0];
        #pragma unroll
        for (int w = 1; w < 8; w++) m = fmaxf(m, sh_red[w]);
        sh_misc[1] = m;
    }
    __syncthreads();
    const float bmax = sh_misc[1];

    float lsum = 0.f;
    for (int u = tid; u < U; u += NTHREADS) {
        float e = expf(sh_scores[u] - bmax);
        sh_scores[u] = e;
        lsum += e;
    }
    #pragma unroll
    for (int off = 16; off; off >>= 1)
        lsum += __shfl_xor_sync(0xffffffffu, lsum, off);
    if (lane == 0) sh_red[wrp] = lsum;
    __syncthreads();
    if (tid == 0) {
        float s = 0.f;
        #pragma unroll
        for (int w = 0; w < 8; w++) s += sh_red[w];
        sh_misc[2] = s;
    }
    __syncthreads();
    const float inv = 1.0f / sh_misc[2];

    for (int u = tid; u < U; u += NTHREADS) {
        float w = sh_scores[u] * inv;
        sh_scores[u] = w;              // normalized, compact (for aggregation)
        sh_wfull[sh_idx[u]] = w;       // scatter to full h index (masked stay 0)
    }
    __syncthreads();

    // ---- Phase F: outputs ----
    // attention_weights [B, 200] at out + B*128
    float* outw = out + (size_t)B_ * EMB_ + (size_t)b * H_;
    for (int t = tid; t < H_ / 4; t += NTHREADS)
        ((float4*)outw)[t] = ((const float4*)sh_wfull)[t];

    // aggregated [B, 128]: weighted sum over compacted rows only
    if (tid < EMB_) {
        float a = 0.f;
        #pragma unroll 4
        for (int u = 0; u < U; u++)
            a = fmaf(sh_scores[u], sh_hist[u * HSTRIDE + tid], a);
        out[(size_t)b * EMB_ + tid] = a;
    }
}

extern "C" void kernel_launch(void* const* d_in, const int* in_sizes, int n_in,
                              void* d_out, int out_size) {
    const float* hist = (const float*)d_in[0];
    const float* cand = (const float*)d_in[1];
    const float* W1   = (const float*)d_in[2];
    const float* b1   = (const float*)d_in[3];
    const float* W2   = (const float*)d_in[4];
    const float* b2   = (const float*)d_in[5];
    const float* W3   = (const float*)d_in[6];
    const float* b3   = (const float*)d_in[7];
    const int*   mask = (const int*)d_in[8];
    float* out = (float*)d_out;

    cudaFuncSetAttribute(attn_agg_kernel,
                         cudaFuncAttributeMaxDynamicSharedMemorySize, SMEM_BYTES);
    attn_agg_kernel<<<B_, NTHREADS, SMEM_BYTES>>>(hist, cand, W1, b1, W2, b2,
                                                  W3, b3, mask, out);
}

// round 17
// speedup vs baseline: 1.0001x; 1.0001x over previous
#include <cuda_runtime.h>
#include <math.h>

#define B_  4096
#define H_  200
#define EMB_ 128
#define HID_ 64
#define HID2_ 32
#define NTHREADS 256
#define HSTRIDE 132     // hist row stride in floats (padded, 16B aligned)
#define H1STRIDE 68     // layer1 output row stride (padded, 16B aligned)

// ---- shared memory layout (offsets in floats, all float4-aligned) ----
#define OFF_HIST   0                       // 200*132 = 26400
#define OFF_W1     26400                   // 128*64  = 8192
#define OFF_W2     34592                   // 64*32   = 2048
#define OFF_H1     36640                   // 64*68   = 4352
#define OFF_CAND   40992                   // 128
#define OFF_WFULL  41120                   // 200
#define OFF_SCORES 41320                   // 200
#define OFF_CPART  41520                   // 64
#define OFF_W3     41584                   // 32
#define OFF_B2     41616                   // 32
#define OFF_RED    41648                   // 32
#define OFF_MISC   41680                   // 4: [0]=count(int) [1]=bmax [2]=bsum [3]=b3
#define OFF_IDX    41684                   // 200 ints
#define SMEM_FLOATS 41884
#define SMEM_BYTES (SMEM_FLOATS * 4)

#define FMA4(ACCROW, AV, W)                      \
    ACCROW[0] = fmaf((AV), (W).x, ACCROW[0]);    \
    ACCROW[1] = fmaf((AV), (W).y, ACCROW[1]);    \
    ACCROW[2] = fmaf((AV), (W).z, ACCROW[2]);    \
    ACCROW[3] = fmaf((AV), (W).w, ACCROW[3]);

__global__ __launch_bounds__(NTHREADS, 1)
void attn_agg_kernel(const float* __restrict__ hist,
                     const float* __restrict__ cand,
                     const float* __restrict__ W1g,
                     const float* __restrict__ b1g,
                     const float* __restrict__ W2g,
                     const float* __restrict__ b2g,
                     const float* __restrict__ W3g,
                     const float* __restrict__ b3g,
                     const int*   __restrict__ maskg,
                     float*       __restrict__ out)
{
    extern __shared__ float sm[];
    float* sh_hist   = sm + OFF_HIST;
    float* sh_W1     = sm + OFF_W1;
    float* sh_W2     = sm + OFF_W2;
    float* sh_H1     = sm + OFF_H1;
    float* sh_cand   = sm + OFF_CAND;
    float* sh_wfull  = sm + OFF_WFULL;
    float* sh_scores = sm + OFF_SCORES;
    float* sh_cpart  = sm + OFF_CPART;
    float* sh_W3     = sm + OFF_W3;
    float* sh_b2     = sm + OFF_B2;
    float* sh_red    = sm + OFF_RED;
    float* sh_misc   = sm + OFF_MISC;
    int*   sh_count  = (int*)(sm + OFF_MISC);
    int*   sh_idx    = (int*)(sm + OFF_IDX);

    const int tid  = threadIdx.x;
    const int b    = blockIdx.x;
    const int lane = tid & 31;
    const int wrp  = tid >> 5;

    // ---- Phase A: compaction (warp 0) + cooperative weight loads (all) ----
    if (wrp == 0) {
        int total = 0;
        const int* mrow = maskg + (size_t)b * H_;
        for (int base = 0; base < H_; base += 32) {
            int h = base + lane;
            int m = (h < H_) ? mrow[h] : 0;
            unsigned bal = __ballot_sync(0xffffffffu, m != 0);
            int rank = __popc(bal & ((1u << lane) - 1u));
            if (m) sh_idx[total + rank] = h;
            total += __popc(bal);
        }
        if (lane == 0) *sh_count = total;
    }
    {
        const float4* W14 = (const float4*)W1g;
        for (int t = tid; t < (EMB_ * HID_) / 4; t += NTHREADS)
            ((float4*)sh_W1)[t] = W14[t];
        const float4* W24 = (const float4*)W2g;
        for (int t = tid; t < (HID_ * HID2_) / 4; t += NTHREADS)
            ((float4*)sh_W2)[t] = W24[t];
        if (tid < 32) { sh_W3[tid] = W3g[tid]; sh_b2[tid] = b2g[tid]; }
        if (tid >= 32 && tid < 64)
            ((float4*)sh_cand)[tid - 32] = ((const float4*)(cand + (size_t)b * EMB_))[tid - 32];
        if (tid == 64) sh_misc[3] = b3g[0];
    }
    __syncthreads();

    int U = *sh_count;
    if (U == 0) {  // all masked: softmax reduces to softmax of raw scores over all h
        for (int h = tid; h < H_; h += NTHREADS) sh_idx[h] = h;
        U = H_;
        __syncthreads();
    }

    // ---- Phase B: candidate part of layer1 (per-b, tiny) ----
    if (tid < HID_) {
        float s = b1g[tid];
        const float* Wb = W1g + (size_t)EMB_ * HID_ + tid;
        #pragma unroll 4
        for (int k = 0; k < EMB_; k++)
            s = fmaf(sh_cand[k], Wb[(size_t)k * HID_], s);
        sh_cpart[tid] = s;
    }

    // ---- Phase C: load ONLY unmasked hist rows (compacted) into SMEM ----
    {
        const float4* hist4 = (const float4*)(hist + (size_t)b * (H_ * EMB_));
        int n = U * 32;
        for (int t = tid; t < n; t += NTHREADS) {
            int u = t >> 5, c = t & 31;
            float4 v = hist4[(size_t)sh_idx[u] * 32 + c];
            *(float4*)&sh_hist[u * HSTRIDE + 4 * c] = v;
        }
    }
    for (int t = tid; t < H_; t += NTHREADS) sh_wfull[t] = 0.f;
    __syncthreads();

    const float b3v = sh_misc[3];

    // ---- Phase D: MLP over compacted rows, 64-row chunks ----
    for (int cb = 0; cb < U; cb += 64) {
        // layer1: [64,128] @ [128,64], 4x4 register tiles, 256 threads
        {
            const int ty = tid >> 4, tx = tid & 15;
            const float* hrow[4];
            #pragma unroll
            for (int i = 0; i < 4; i++) {
                int r = cb + 4 * ty + i;
                if (r > U - 1) r = U - 1;       // clamp (garbage rows discarded later)
                hrow[i] = sh_hist + r * HSTRIDE;
            }
            float acc[4][4];
            #pragma unroll
            for (int i = 0; i < 4; i++)
                #pragma unroll
                for (int j = 0; j < 4; j++) acc[i][j] = 0.f;

            const float* wp = sh_W1 + 4 * tx;
            #pragma unroll 4
            for (int k = 0; k < EMB_; k += 4) {
                float4 a0 = *(const float4*)(hrow[0] + k);
                float4 a1 = *(const float4*)(hrow[1] + k);
                float4 a2 = *(const float4*)(hrow[2] + k);
                float4 a3 = *(const float4*)(hrow[3] + k);
                float4 w0 = *(const float4*)(wp + (k + 0) * HID_);
                float4 w1 = *(const float4*)(wp + (k + 1) * HID_);
                float4 w2 = *(const float4*)(wp + (k + 2) * HID_);
                float4 w3 = *(const float4*)(wp + (k + 3) * HID_);
                FMA4(acc[0], a0.x, w0) FMA4(acc[1], a1.x, w0) FMA4(acc[2], a2.x, w0) FMA4(acc[3], a3.x, w0)
                FMA4(acc[0], a0.y, w1) FMA4(acc[1], a1.y, w1) FMA4(acc[2], a2.y, w1) FMA4(acc[3], a3.y, w1)
                FMA4(acc[0], a0.z, w2) FMA4(acc[1], a1.z, w2) FMA4(acc[2], a2.z, w2) FMA4(acc[3], a3.z, w2)
                FMA4(acc[0], a0.w, w3) FMA4(acc[1], a1.w, w3) FMA4(acc[2], a2.w, w3) FMA4(acc[3], a3.w, w3)
            }
            float4 cp = *(const float4*)(sh_cpart + 4 * tx);
            #pragma unroll
            for (int i = 0; i < 4; i++) {
                float4 v;
                v.x = fmaxf(acc[i][0] + cp.x, 0.f);
                v.y = fmaxf(acc[i][1] + cp.y, 0.f);
                v.z = fmaxf(acc[i][2] + cp.z, 0.f);
                v.w = fmaxf(acc[i][3] + cp.w, 0.f);
                *(float4*)&sh_H1[(4 * ty + i) * H1STRIDE + 4 * tx] = v;
            }
        }
        __syncthreads();

        // layer2+3: [64,64]@[64,32] then dot with W3, 128 threads, 4x4 tiles
        if (tid < 128) {
            const int ty2 = tid >> 3, tx2 = tid & 7;
            const float* h1p = sh_H1 + (4 * ty2) * H1STRIDE;
            float acc2[4][4];
            #pragma unroll
            for (int i = 0; i < 4; i++)
                #pragma unroll
                for (int j = 0; j < 4; j++) acc2[i][j] = 0.f;

            const float* wp2 = sh_W2 + 4 * tx2;
            #pragma unroll 4
            for (int k = 0; k < HID_; k += 4) {
                float4 a0 = *(const float4*)(h1p + 0 * H1STRIDE + k);
                float4 a1 = *(const float4*)(h1p + 1 * H1STRIDE + k);
                float4 a2 = *(const float4*)(h1p + 2 * H1STRIDE + k);
                float4 a3 = *(const float4*)(h1p + 3 * H1STRIDE + k);
                float4 w0 = *(const float4*)(wp2 + (k + 0) * HID2_);
                float4 w1 = *(const float4*)(wp2 + (k + 1) * HID2_);
                float4 w2 = *(const float4*)(wp2 + (k + 2) * HID2_);
                float4 w3 = *(const float4*)(wp2 + (k + 3) * HID2_);
                FMA4(acc2[0], a0.x, w0) FMA4(acc2[1], a1.x, w0) FMA4(acc2[2], a2.x, w0) FMA4(acc2[3], a3.x, w0)
                FMA4(acc2[0], a0.y, w1) FMA4(acc2[1], a1.y, w1) FMA4(acc2[2], a2.y, w1) FMA4(acc2[3], a3.y, w1)
                FMA4(acc2[0], a0.z, w2) FMA4(acc2[1], a1.z, w2) FMA4(acc2[2], a2.z, w2) FMA4(acc2[3], a3.z, w2)
                FMA4(acc2[0], a0.w, w3) FMA4(acc2[1], a1.w, w3) FMA4(acc2[2], a2.w, w3) FMA4(acc2[3], a3.w, w3)
            }
            float4 bb  = *(const float4*)(sh_b2 + 4 * tx2);
            float4 w3c = *(const float4*)(sh_W3 + 4 * tx2);
            #pragma unroll
            for (int i = 0; i < 4; i++) {
                float v0 = fmaxf(acc2[i][0] + bb.x, 0.f);
                float v1 = fmaxf(acc2[i][1] + bb.y, 0.f);
                float v2 = fmaxf(acc2[i][2] + bb.z, 0.f);
                float v3 = fmaxf(acc2[i][3] + bb.w, 0.f);
                float p = v0 * w3c.x + v1 * w3c.y + v2 * w3c.z + v3 * w3c.w;
                p += __shfl_down_sync(0xffffffffu, p, 4, 8);
                p += __shfl_down_sync(0xffffffffu, p, 2, 8);
                p += __shfl_down_sync(0xffffffffu, p, 1, 8);
                if (tx2 == 0) {
                    int g = cb + 4 * ty2 + i;
                    if (g < U) sh_scores[g] = p + b3v;
                }
            }
        }
        __syncthreads();
    }

    // ---- Phase E: softmax over compacted scores ----
    float lmax = -3.0e38f;
    for (int u = tid; u < U; u += NTHREADS) lmax = fmaxf(lmax, sh_scores[u]);
    #pragma unroll
    for (int off = 16; off; off >>= 1)
        lmax = fmaxf(lmax, __shfl_xor_sync(0xffffffffu, lmax, off));
    if (lane == 0) sh_red[wrp] = lmax;
    __syncthreads();
    if (tid == 0) {
        float m = sh_red[0];
        #pragma unroll
        for (int w = 1; w < 8; w++) m = fmaxf(m, sh_red[w]);
        sh_misc[1] = m;
    }
    __syncthreads();
    const float bmax = sh_misc[1];

    float lsum = 0.f;
    for (int u = tid; u < U; u += NTHREADS) {
        float e = expf(sh_scores[u] - bmax);
        sh_scores[u] = e;
        lsum += e;
    }
    #pragma unroll
    for (int off = 16; off; off >>= 1)
        lsum += __shfl_xor_sync(0xffffffffu, lsum, off);
    if (lane == 0) sh_red[wrp] = lsum;
    __syncthreads();
    if (tid == 0) {
        float s = 0.f;
        #pragma unroll
        for (int w = 0; w < 8; w++) s += sh_red[w];
        sh_misc[2] = s;
    }
    __syncthreads();
    const float inv = 1.0f / sh_misc[2];

    for (int u = tid; u < U; u += NTHREADS) {
        float w = sh_scores[u] * inv;
        sh_scores[u] = w;              // normalized, compact (for aggregation)
        sh_wfull[sh_idx[u]] = w;       // scatter to full h index (masked stay 0)
    }
    __syncthreads();

    // ---- Phase F: outputs ----
    // attention_weights [B, 200] at out + B*128
    float* outw = out + (size_t)B_ * EMB_ + (size_t)b * H_;
    for (int t = tid; t < H_ / 4; t += NTHREADS)
        ((float4*)outw)[t] = ((const float4*)sh_wfull)[t];

    // aggregated [B, 128]: weighted sum over compacted rows only
    if (tid < EMB_) {
        float a = 0.f;
        #pragma unroll 4
        for (int u = 0; u < U; u++)
            a = fmaf(sh_scores[u], sh_hist[u * HSTRIDE + tid], a);
        out[(size_t)b * EMB_ + tid] = a;
    }
}

extern "C" void kernel_launch(void* const* d_in, const int* in_sizes, int n_in,
                              void* d_out, int out_size) {
    const float* hist = (const float*)d_in[0];
    const float* cand = (const float*)d_in[1];
    const float* W1   = (const float*)d_in[2];
    const float* b1   = (const float*)d_in[3];
    const float* W2   = (const float*)d_in[4];
    const float* b2   = (const float*)d_in[5];
    const float* W3   = (const float*)d_in[6];
    const float* b3   = (const float*)d_in[7];
    const int*   mask = (const int*)d_in[8];
    float* out = (float*)d_out;

    cudaFuncSetAttribute(attn_agg_kernel,
                         cudaFuncAttributeMaxDynamicSharedMemorySize, SMEM_BYTES);
    attn_agg_kernel<<<B_, NTHREADS, SMEM_BYTES>>>(hist, cand, W1, b1, W2, b2,
                                                  W3, b3, mask, out);
}